// round 2
// baseline (speedup 1.0000x reference)
#include <cuda_runtime.h>

#define B_   256
#define K_   256
#define C_   128
#define KG_  64
#define OUTC 117
#define OCH  183

// scratch (allocation-free rule: __device__ globals)
__device__ float g_net1[B_ * C_ * K_];   // pre-BN layer1 output (B,128,256)
__device__ float g_net2[B_ * C_ * K_];   // pre-BN layer2 output
__device__ float g_t[B_ * OUTC * K_];    // layer3 output (B,117,256)
__device__ float g_a1[C_], g_d1[C_], g_a2[C_], g_d2[C_];

// ---------------------------------------------------------------------------
// objectness_label: per (b,k) min squared distance to 64 gt centers
// ---------------------------------------------------------------------------
__global__ void label_kernel(const float* __restrict__ xyz,
                             const float* __restrict__ gt,
                             float* __restrict__ lbl) {
    int b = blockIdx.x, k = threadIdx.x;
    __shared__ float sg[KG_ * 3];
    if (k < KG_ * 3) sg[k] = gt[b * KG_ * 3 + k];
    __syncthreads();
    const float* p = xyz + (b * K_ + k) * 3;
    float x = p[0], y = p[1], z = p[2];
    float mn = 1e30f;
#pragma unroll 8
    for (int g = 0; g < KG_; g++) {
        float dx = x - sg[g * 3 + 0];
        float dy = y - sg[g * 3 + 1];
        float dz = z - sg[g * 3 + 2];
        float d = dx * dx + dy * dy + dz * dz;
        mn = fminf(mn, d);
    }
    float e = sqrtf(mn + 1e-6f);
    lbl[b * K_ + k] = (e < 0.3f) ? 1.0f : 0.0f;
}

// ---------------------------------------------------------------------------
// get_index: sorted-key compaction == [ascending object indices, then k]
// NOTE: objectness_pred arrives as int32 (JAX x64 disabled), NOT int64.
// ---------------------------------------------------------------------------
__global__ void index_kernel(const int* __restrict__ pred,
                             float* __restrict__ idxo,
                             float* __restrict__ sum1) {
    int b = blockIdx.x, k = threadIdx.x;
    int p = pred[b * K_ + k];
    __shared__ int sc[K_];
    __shared__ int res[K_];
    sc[k] = p;
    res[k] = k;
    __syncthreads();
    // Hillis-Steele inclusive scan
    for (int off = 1; off < K_; off <<= 1) {
        int add = (k >= off) ? sc[k - off] : 0;
        __syncthreads();
        sc[k] += add;
        __syncthreads();
    }
    int num = sc[K_ - 1];
    int excl = sc[k] - p;
    if (p == 1) res[excl] = k;
    __syncthreads();
    idxo[b * K_ + k] = (float)((k < num) ? res[k] : k);
    if (k == 0) sum1[b] = (float)num;
}

// ---------------------------------------------------------------------------
// Batched GEMM: Y[b,m,k] = sum_c W[m,c] * X[b,c,k] + bias[m]
// MODE 0: X = concat(X0, X1) along c (CIN=256)
// MODE 1: X = relu(X0 * a[c] + d[c])  (fused BN+relu on load, CIN=128)
// Tiling: BM=64 BN=64 BK=16, 256 threads, 4x4 register tile.
// ---------------------------------------------------------------------------
template <int CIN, int MODE>
__global__ void gemm_kernel(const float* __restrict__ W,
                            const float* __restrict__ bias,
                            const float* __restrict__ X0,
                            const float* __restrict__ X1,
                            const float* __restrict__ aa,
                            const float* __restrict__ dd,
                            float* __restrict__ Y, int M) {
    const int BM = 64, BN = 64, BK = 16;
    __shared__ float As[BK][BM + 1];  // [c][m], padded against write conflicts
    __shared__ float Bs[BK][BN];      // [c][n]
    __shared__ float sA[C_], sD[C_];

    int tid = threadIdx.x;
    int b = blockIdx.z;
    int n0 = blockIdx.x * BN;
    int m0 = blockIdx.y * BM;

    if (MODE == 1) {
        if (tid < C_) { sA[tid] = aa[tid]; sD[tid] = dd[tid]; }
    }
    __syncthreads();

    float acc[4][4] = {};
    int tm = (tid >> 4) * 4;
    int tn = (tid & 15) * 4;

    for (int c0 = 0; c0 < CIN; c0 += BK) {
        // load W tile -> As[c][m]
#pragma unroll
        for (int i = 0; i < 4; i++) {
            int li = tid + i * 256;
            int m = li >> 4, c = li & 15;
            float w = (m0 + m < M) ? W[(m0 + m) * CIN + c0 + c] : 0.f;
            As[c][m] = w;
        }
        // load X tile -> Bs[c][n]  (coalesced along n)
#pragma unroll
        for (int i = 0; i < 4; i++) {
            int li = tid + i * 256;
            int c = li >> 6, n = li & 63;
            int cg = c0 + c;
            float v;
            if (MODE == 0) {
                v = (cg < C_) ? X0[b * C_ * K_ + cg * K_ + n0 + n]
                              : X1[b * C_ * K_ + (cg - C_) * K_ + n0 + n];
            } else {
                v = X0[b * C_ * K_ + cg * K_ + n0 + n];
                v = fmaxf(fmaf(v, sA[cg], sD[cg]), 0.f);
            }
            Bs[c][n] = v;
        }
        __syncthreads();
#pragma unroll
        for (int kk = 0; kk < BK; kk++) {
            float ra[4], rb[4];
#pragma unroll
            for (int i = 0; i < 4; i++) ra[i] = As[kk][tm + i];
            float4 bv = *reinterpret_cast<const float4*>(&Bs[kk][tn]);
            rb[0] = bv.x; rb[1] = bv.y; rb[2] = bv.z; rb[3] = bv.w;
#pragma unroll
            for (int i = 0; i < 4; i++)
#pragma unroll
                for (int j = 0; j < 4; j++)
                    acc[i][j] = fmaf(ra[i], rb[j], acc[i][j]);
        }
        __syncthreads();
    }

#pragma unroll
    for (int i = 0; i < 4; i++) {
        int m = m0 + tm + i;
        if (m < M) {
            float bb = bias[m];
#pragma unroll
            for (int j = 0; j < 4; j++)
                Y[b * M * K_ + m * K_ + n0 + tn + j] = acc[i][j] + bb;
        }
    }
}

// ---------------------------------------------------------------------------
// BN statistics over axes (0,2) for channel c; fold gamma/beta into (a,d):
// relu_bn(x) = relu(x * a + d)
// ---------------------------------------------------------------------------
__global__ void stats_kernel(const float* __restrict__ X,
                             const float* __restrict__ g,
                             const float* __restrict__ be,
                             float* __restrict__ a, float* __restrict__ d) {
    int c = blockIdx.x, tid = threadIdx.x;
    float s = 0.f, s2 = 0.f;
    for (int i = tid; i < B_ * K_; i += 256) {
        float v = X[(i >> 8) * (C_ * K_) + c * K_ + (i & 255)];
        s += v;
        s2 += v * v;
    }
    __shared__ float ss[256], ss2[256];
    ss[tid] = s; ss2[tid] = s2;
    __syncthreads();
    for (int off = 128; off > 0; off >>= 1) {
        if (tid < off) { ss[tid] += ss[tid + off]; ss2[tid] += ss2[tid + off]; }
        __syncthreads();
    }
    if (tid == 0) {
        const float invN = 1.0f / (B_ * K_);
        float mean = ss[0] * invN;
        float var = ss2[0] * invN - mean * mean;
        float rstd = rsqrtf(var + 1e-5f);
        float av = rstd * g[c];
        a[c] = av;
        d[c] = be[c] - mean * av;
    }
}

// ---------------------------------------------------------------------------
// Assemble the 183-channel output (coalesced: one thread per output element)
// ---------------------------------------------------------------------------
__global__ void epilogue_kernel(const float* __restrict__ xyz,
                                const float* __restrict__ ms,
                                float* __restrict__ out) {
    int t = blockIdx.x * 256 + threadIdx.x;
    if (t >= B_ * K_ * OCH) return;
    int ch = t % OCH;
    int bk = t / OCH;
    int k = bk & (K_ - 1);
    int b = bk >> 8;

    int o;
    float scale = 1.f, add = 0.f;
    if (ch < 27) {               // center(+xyz), hs, hrn
        o = ch;
        if (ch < 3) add = xyz[bk * 3 + ch];
    } else if (ch < 39) {        // hr = hrn * pi/12
        o = ch - 12;
        scale = 0.26179938779914943f;
    } else if (ch < 111) {       // ss, srn
        o = ch - 12;
    } else if (ch < 165) {       // sr = srn * mean_size
        o = ch - 66;
        scale = ms[ch - 111];
    } else {                     // sem
        o = ch - 66;
    }
    out[t] = g_t[b * OUTC * K_ + o * K_ + k] * scale + add;
}

// ---------------------------------------------------------------------------
extern "C" void kernel_launch(void* const* d_in, const int* in_sizes, int n_in,
                              void* d_out, int out_size) {
    (void)in_sizes; (void)n_in; (void)out_size;
    const float* xyz      = (const float*)d_in[0];
    const float* features = (const float*)d_in[1];
    const float* rn       = (const float*)d_in[2];
    const float* gt       = (const float*)d_in[3];
    const int*   pred     = (const int*)d_in[4];   // int32 (JAX x64 disabled)
    const float* W1 = (const float*)d_in[5];
    const float* b1 = (const float*)d_in[6];
    const float* g1 = (const float*)d_in[7];
    const float* be1 = (const float*)d_in[8];
    const float* W2 = (const float*)d_in[9];
    const float* b2 = (const float*)d_in[10];
    const float* g2 = (const float*)d_in[11];
    const float* be2 = (const float*)d_in[12];
    const float* W3 = (const float*)d_in[13];
    const float* b3 = (const float*)d_in[14];
    const float* ms = (const float*)d_in[15];
    float* out = (float*)d_out;

    // output layout: out(11993088) | idx_obj(65536) | sum_1(256) | label(65536)
    const int OFF_IDX = B_ * K_ * OCH;           // 11993088
    const int OFF_SUM = OFF_IDX + B_ * K_;       // 12058624
    const int OFF_LBL = OFF_SUM + B_;            // 12058880

    float *p_net1, *p_net2, *p_t, *p_a1, *p_d1, *p_a2, *p_d2;
    cudaGetSymbolAddress((void**)&p_net1, g_net1);
    cudaGetSymbolAddress((void**)&p_net2, g_net2);
    cudaGetSymbolAddress((void**)&p_t,    g_t);
    cudaGetSymbolAddress((void**)&p_a1,   g_a1);
    cudaGetSymbolAddress((void**)&p_d1,   g_d1);
    cudaGetSymbolAddress((void**)&p_a2,   g_a2);
    cudaGetSymbolAddress((void**)&p_d2,   g_d2);

    label_kernel<<<B_, K_>>>(xyz, gt, out + OFF_LBL);
    index_kernel<<<B_, K_>>>(pred, out + OFF_IDX, out + OFF_SUM);

    dim3 gg(K_ / 64, 2, B_);  // (n-tiles, m-tiles, batch)
    gemm_kernel<256, 0><<<gg, 256>>>(W1, b1, features, rn, nullptr, nullptr, p_net1, C_);
    stats_kernel<<<C_, 256>>>(p_net1, g1, be1, p_a1, p_d1);
    gemm_kernel<128, 1><<<gg, 256>>>(W2, b2, p_net1, nullptr, p_a1, p_d1, p_net2, C_);
    stats_kernel<<<C_, 256>>>(p_net2, g2, be2, p_a2, p_d2);
    gemm_kernel<128, 1><<<gg, 256>>>(W3, b3, p_net2, nullptr, p_a2, p_d2, p_t, OUTC);

    int total = B_ * K_ * OCH;
    epilogue_kernel<<<(total + 255) / 256, 256>>>(xyz, ms, out);
}

// round 4
// speedup vs baseline: 1.1436x; 1.1436x over previous
#include <cuda_runtime.h>

#define B_   256
#define K_   256
#define C_   128
#define KG_  64
#define OUTC 117
#define OCH  183

// scratch (allocation-free rule: __device__ globals)
__device__ float g_net1[B_ * C_ * K_];   // pre-BN layer1 output (B,128,256)
__device__ float g_net2[B_ * C_ * K_];   // pre-BN layer2 output
__device__ float g_t[B_ * OUTC * K_];    // layer3 output (B,117,256)
__device__ float g_s[2][C_];             // BN sum accumulators (layer 1,2)
__device__ float g_s2[2][C_];            // BN sum-of-squares accumulators
__device__ float g_a[2][C_], g_d[2][C_]; // folded BN scale/shift

// ---------------------------------------------------------------------------
__global__ void zero_kernel() {
    int t = threadIdx.x;
    if (t < C_) {
        g_s[0][t] = 0.f; g_s[1][t] = 0.f;
        g_s2[0][t] = 0.f; g_s2[1][t] = 0.f;
    }
}

// ---------------------------------------------------------------------------
// objectness_label: per (b,k) min squared distance to 64 gt centers
// ---------------------------------------------------------------------------
__global__ void label_kernel(const float* __restrict__ xyz,
                             const float* __restrict__ gt,
                             float* __restrict__ lbl) {
    int b = blockIdx.x, k = threadIdx.x;
    __shared__ float sg[KG_ * 3];
    if (k < KG_ * 3) sg[k] = gt[b * KG_ * 3 + k];
    __syncthreads();
    const float* p = xyz + (b * K_ + k) * 3;
    float x = p[0], y = p[1], z = p[2];
    float mn = 1e30f;
#pragma unroll 8
    for (int g = 0; g < KG_; g++) {
        float dx = x - sg[g * 3 + 0];
        float dy = y - sg[g * 3 + 1];
        float dz = z - sg[g * 3 + 2];
        float d = dx * dx + dy * dy + dz * dz;
        mn = fminf(mn, d);
    }
    float e = sqrtf(mn + 1e-6f);
    lbl[b * K_ + k] = (e < 0.3f) ? 1.0f : 0.0f;
}

// ---------------------------------------------------------------------------
// get_index (objectness_pred is int32: JAX x64 disabled)
// ---------------------------------------------------------------------------
__global__ void index_kernel(const int* __restrict__ pred,
                             float* __restrict__ idxo,
                             float* __restrict__ sum1) {
    int b = blockIdx.x, k = threadIdx.x;
    int p = pred[b * K_ + k];
    __shared__ int sc[K_];
    __shared__ int res[K_];
    sc[k] = p;
    res[k] = k;
    __syncthreads();
    for (int off = 1; off < K_; off <<= 1) {
        int add = (k >= off) ? sc[k - off] : 0;
        __syncthreads();
        sc[k] += add;
        __syncthreads();
    }
    int num = sc[K_ - 1];
    int excl = sc[k] - p;
    if (p == 1) res[excl] = k;
    __syncthreads();
    idxo[b * K_ + k] = (float)((k < num) ? res[k] : k);
    if (k == 0) sum1[b] = (float)num;
}

// ---------------------------------------------------------------------------
// Batched GEMM: Y[b,m,k] = sum_c W[m,c] * X[b,c,k] + bias[m]
// MODE 0: X = concat(X0, X1) along c (CIN=256)
// MODE 1: X = relu(X0 * a[c] + d[c])  (fused BN+relu on load, CIN=128)
// STATS : accumulate per-channel sum / sum^2 of (Y) into sS/sS2 via atomics
// Tiling: BM=128 BN=128 BK=16, 256 threads, 8x8 register tile.
// As row stride = BM+4 = 132 -> every row 16B-aligned for LDS.128.
// ---------------------------------------------------------------------------
template <int CIN, int MODE, int STATS>
__global__ void __launch_bounds__(256)
gemm_kernel(const float* __restrict__ W,
            const float* __restrict__ bias,
            const float* __restrict__ X0,
            const float* __restrict__ X1,
            const float* __restrict__ aa,
            const float* __restrict__ dd,
            float* __restrict__ Y, int M,
            float* __restrict__ sS, float* __restrict__ sS2) {
    const int BM = 128, BN = 128, BK = 16;
    const int AS = BM + 4;            // 132: keeps 16B alignment per row
    __shared__ float As[BK][AS];      // [c][m]
    __shared__ float Bs[BK][BN];      // [c][n]

    int tid = threadIdx.x;
    int b = blockIdx.z;
    int n0 = blockIdx.x * BN;
    int m0 = blockIdx.y * BM;

    float acc[8][8] = {};
    int tm = (tid >> 4) * 8;
    int tn = (tid & 15) * 8;

    // A-load mapping: m = tid>>1 (0..127), c = (tid&1)*8 -> 2 float4 along c
    int am = tid >> 1;
    int ac = (tid & 1) * 8;
    // B-load mapping: c = tid>>4 (0..15), n = (tid&15)*8 -> 2 float4 along n
    int bc = tid >> 4;
    int bn = (tid & 15) * 8;

    for (int c0 = 0; c0 < CIN; c0 += BK) {
        // --- load W tile -> As[c][m] ---
        float4 w0, w1;
        if (m0 + am < M) {
            const float* wp = W + (m0 + am) * CIN + c0 + ac;
            w0 = *reinterpret_cast<const float4*>(wp);
            w1 = *reinterpret_cast<const float4*>(wp + 4);
        } else {
            w0 = make_float4(0.f, 0.f, 0.f, 0.f);
            w1 = w0;
        }
        As[ac + 0][am] = w0.x; As[ac + 1][am] = w0.y;
        As[ac + 2][am] = w0.z; As[ac + 3][am] = w0.w;
        As[ac + 4][am] = w1.x; As[ac + 5][am] = w1.y;
        As[ac + 6][am] = w1.z; As[ac + 7][am] = w1.w;

        // --- load X tile -> Bs[c][n] (coalesced along n) ---
        {
            int cg = c0 + bc;
            float4 v0, v1;
            if (MODE == 0) {
                const float* xp = (cg < C_)
                    ? X0 + b * C_ * K_ + cg * K_ + n0 + bn
                    : X1 + b * C_ * K_ + (cg - C_) * K_ + n0 + bn;
                v0 = *reinterpret_cast<const float4*>(xp);
                v1 = *reinterpret_cast<const float4*>(xp + 4);
            } else {
                const float* xp = X0 + b * C_ * K_ + cg * K_ + n0 + bn;
                v0 = *reinterpret_cast<const float4*>(xp);
                v1 = *reinterpret_cast<const float4*>(xp + 4);
                float av = aa[cg], dv = dd[cg];
                v0.x = fmaxf(fmaf(v0.x, av, dv), 0.f);
                v0.y = fmaxf(fmaf(v0.y, av, dv), 0.f);
                v0.z = fmaxf(fmaf(v0.z, av, dv), 0.f);
                v0.w = fmaxf(fmaf(v0.w, av, dv), 0.f);
                v1.x = fmaxf(fmaf(v1.x, av, dv), 0.f);
                v1.y = fmaxf(fmaf(v1.y, av, dv), 0.f);
                v1.z = fmaxf(fmaf(v1.z, av, dv), 0.f);
                v1.w = fmaxf(fmaf(v1.w, av, dv), 0.f);
            }
            *reinterpret_cast<float4*>(&Bs[bc][bn]) = v0;
            *reinterpret_cast<float4*>(&Bs[bc][bn + 4]) = v1;
        }
        __syncthreads();

#pragma unroll
        for (int kk = 0; kk < BK; kk++) {
            float ra[8], rb[8];
            float4 a0 = *reinterpret_cast<const float4*>(&As[kk][tm]);
            float4 a1 = *reinterpret_cast<const float4*>(&As[kk][tm + 4]);
            float4 b0 = *reinterpret_cast<const float4*>(&Bs[kk][tn]);
            float4 b1 = *reinterpret_cast<const float4*>(&Bs[kk][tn + 4]);
            ra[0] = a0.x; ra[1] = a0.y; ra[2] = a0.z; ra[3] = a0.w;
            ra[4] = a1.x; ra[5] = a1.y; ra[6] = a1.z; ra[7] = a1.w;
            rb[0] = b0.x; rb[1] = b0.y; rb[2] = b0.z; rb[3] = b0.w;
            rb[4] = b1.x; rb[5] = b1.y; rb[6] = b1.z; rb[7] = b1.w;
#pragma unroll
            for (int i = 0; i < 8; i++)
#pragma unroll
                for (int j = 0; j < 8; j++)
                    acc[i][j] = fmaf(ra[i], rb[j], acc[i][j]);
        }
        __syncthreads();
    }

    // --- store (+bias), with fused BN-stat accumulation ---
#pragma unroll
    for (int i = 0; i < 8; i++) {
        int m = m0 + tm + i;
        if (m < M) {
            float bb = __ldg(bias + m);
            float s = 0.f, s2 = 0.f;
            float* yp = Y + b * M * K_ + m * K_ + n0 + tn;
#pragma unroll
            for (int j = 0; j < 8; j++) {
                float v = acc[i][j] + bb;
                yp[j] = v;
                if (STATS) { s += v; s2 = fmaf(v, v, s2); }
            }
            if (STATS) {
                // reduce over the 16 lanes (tid&15) sharing channel m
#pragma unroll
                for (int o = 8; o > 0; o >>= 1) {
                    s  += __shfl_xor_sync(0xffffffffu, s,  o);
                    s2 += __shfl_xor_sync(0xffffffffu, s2, o);
                }
                if ((tid & 15) == 0) {
                    atomicAdd(&sS[m], s);
                    atomicAdd(&sS2[m], s2);
                }
            }
        }
    }
}

// ---------------------------------------------------------------------------
// finalize BN fold: relu_bn(x) = relu(x*a + d)
// ---------------------------------------------------------------------------
__global__ void finalize_kernel(const float* __restrict__ g,
                                const float* __restrict__ be,
                                const float* __restrict__ sS,
                                const float* __restrict__ sS2,
                                float* __restrict__ a, float* __restrict__ d) {
    int c = threadIdx.x;
    if (c < C_) {
        const float invN = 1.0f / (B_ * K_);
        float mean = sS[c] * invN;
        float var = sS2[c] * invN - mean * mean;
        float rstd = rsqrtf(var + 1e-5f);
        float av = rstd * g[c];
        a[c] = av;
        d[c] = be[c] - mean * av;
    }
}

// ---------------------------------------------------------------------------
// Assemble the 183-channel output. SMEM transpose: load g_t coalesced along k,
// write out coalesced along ch. block = (k-chunk of 64, b), 256 threads.
// ---------------------------------------------------------------------------
__global__ void epilogue_kernel(const float* __restrict__ xyz,
                                const float* __restrict__ ms,
                                float* __restrict__ out) {
    __shared__ float s[OUTC * 65];   // [o][k] padded
    __shared__ float sms[54];
    int tid = threadIdx.x;
    int k0 = blockIdx.x * 64;
    int b = blockIdx.y;

    if (tid < 54) sms[tid] = ms[tid];
    const float* tp = g_t + b * OUTC * K_ + k0;
    for (int e = tid; e < OUTC * 64; e += 256) {
        int o = e >> 6, k = e & 63;
        s[o * 65 + k] = tp[o * K_ + k];
    }
    __syncthreads();

    float* op = out + (b * K_ + k0) * OCH;
    for (int e = tid; e < 64 * OCH; e += 256) {
        int k = e / OCH;
        int ch = e - k * OCH;
        int o;
        float scale = 1.f, add = 0.f;
        if (ch < 27) {               // center(+xyz), hs, hrn
            o = ch;
            if (ch < 3) add = xyz[(b * K_ + k0 + k) * 3 + ch];
        } else if (ch < 39) {        // hr = hrn * pi/12
            o = ch - 12;
            scale = 0.26179938779914943f;
        } else if (ch < 111) {       // ss, srn
            o = ch - 12;
        } else if (ch < 165) {       // sr = srn * mean_size
            o = ch - 66;
            scale = sms[ch - 111];
        } else {                     // sem
            o = ch - 66;
        }
        op[e] = s[o * 65 + k] * scale + add;
    }
}

// ---------------------------------------------------------------------------
extern "C" void kernel_launch(void* const* d_in, const int* in_sizes, int n_in,
                              void* d_out, int out_size) {
    (void)in_sizes; (void)n_in; (void)out_size;
    const float* xyz      = (const float*)d_in[0];
    const float* features = (const float*)d_in[1];
    const float* rn       = (const float*)d_in[2];
    const float* gt       = (const float*)d_in[3];
    const int*   pred     = (const int*)d_in[4];   // int32
    const float* W1 = (const float*)d_in[5];
    const float* b1 = (const float*)d_in[6];
    const float* g1 = (const float*)d_in[7];
    const float* be1 = (const float*)d_in[8];
    const float* W2 = (const float*)d_in[9];
    const float* b2 = (const float*)d_in[10];
    const float* g2 = (const float*)d_in[11];
    const float* be2 = (const float*)d_in[12];
    const float* W3 = (const float*)d_in[13];
    const float* b3 = (const float*)d_in[14];
    const float* ms = (const float*)d_in[15];
    float* out = (float*)d_out;

    const int OFF_IDX = B_ * K_ * OCH;           // 11993088
    const int OFF_SUM = OFF_IDX + B_ * K_;       // 12058624
    const int OFF_LBL = OFF_SUM + B_;            // 12058880

    float *p_net1, *p_net2, *p_t, *p_s, *p_s2, *p_a, *p_d;
    cudaGetSymbolAddress((void**)&p_net1, g_net1);
    cudaGetSymbolAddress((void**)&p_net2, g_net2);
    cudaGetSymbolAddress((void**)&p_t,    g_t);
    cudaGetSymbolAddress((void**)&p_s,    g_s);
    cudaGetSymbolAddress((void**)&p_s2,   g_s2);
    cudaGetSymbolAddress((void**)&p_a,    g_a);
    cudaGetSymbolAddress((void**)&p_d,    g_d);

    zero_kernel<<<1, 128>>>();
    label_kernel<<<B_, K_>>>(xyz, gt, out + OFF_LBL);
    index_kernel<<<B_, K_>>>(pred, out + OFF_IDX, out + OFF_SUM);

    dim3 gg(K_ / 128, 1, B_);  // (n-tiles, m-tiles, batch)
    gemm_kernel<256, 0, 1><<<gg, 256>>>(W1, b1, features, rn, nullptr, nullptr,
                                        p_net1, C_, p_s, p_s2);
    finalize_kernel<<<1, 128>>>(g1, be1, p_s, p_s2, p_a, p_d);
    gemm_kernel<128, 1, 1><<<gg, 256>>>(W2, b2, p_net1, nullptr, p_a, p_d,
                                        p_net2, C_, p_s + C_, p_s2 + C_);
    finalize_kernel<<<1, 128>>>(g2, be2, p_s + C_, p_s2 + C_, p_a + C_, p_d + C_);
    gemm_kernel<128, 1, 0><<<gg, 256>>>(W3, b3, p_net2, nullptr, p_a + C_, p_d + C_,
                                        p_t, OUTC, nullptr, nullptr);

    epilogue_kernel<<<dim3(K_ / 64, B_), 256>>>(xyz, ms, out);
}

// round 5
// speedup vs baseline: 1.1444x; 1.0007x over previous
#include <cuda_runtime.h>

#define B_   256
#define K_   256
#define C_   128
#define KG_  64
#define OUTC 117
#define OCH  183

// scratch (allocation-free rule: __device__ globals)
__device__ float g_net1[B_ * C_ * K_];   // pre-BN layer1 output (B,128,256)
__device__ float g_net2[B_ * C_ * K_];   // pre-BN layer2 output
__device__ float g_t[B_ * OUTC * K_];    // layer3 output (B,117,256)
__device__ float g_s[2][C_];             // BN sum accumulators (layer 1,2)
__device__ float g_s2[2][C_];            // BN sum-of-squares accumulators
__device__ float g_a[2][C_], g_d[2][C_]; // folded BN scale/shift

// ---------------------------------------------------------------------------
__global__ void zero_kernel() {
    int t = threadIdx.x;
    if (t < C_) {
        g_s[0][t] = 0.f; g_s[1][t] = 0.f;
        g_s2[0][t] = 0.f; g_s2[1][t] = 0.f;
    }
}

// ---------------------------------------------------------------------------
// objectness_label: per (b,k) min squared distance to 64 gt centers
// ---------------------------------------------------------------------------
__global__ void label_kernel(const float* __restrict__ xyz,
                             const float* __restrict__ gt,
                             float* __restrict__ lbl) {
    int b = blockIdx.x, k = threadIdx.x;
    __shared__ float sg[KG_ * 3];
    if (k < KG_ * 3) sg[k] = gt[b * KG_ * 3 + k];
    __syncthreads();
    const float* p = xyz + (b * K_ + k) * 3;
    float x = p[0], y = p[1], z = p[2];
    float mn = 1e30f;
#pragma unroll 8
    for (int g = 0; g < KG_; g++) {
        float dx = x - sg[g * 3 + 0];
        float dy = y - sg[g * 3 + 1];
        float dz = z - sg[g * 3 + 2];
        float d = dx * dx + dy * dy + dz * dz;
        mn = fminf(mn, d);
    }
    float e = sqrtf(mn + 1e-6f);
    lbl[b * K_ + k] = (e < 0.3f) ? 1.0f : 0.0f;
}

// ---------------------------------------------------------------------------
// get_index (objectness_pred is int32: JAX x64 disabled)
// ---------------------------------------------------------------------------
__global__ void index_kernel(const int* __restrict__ pred,
                             float* __restrict__ idxo,
                             float* __restrict__ sum1) {
    int b = blockIdx.x, k = threadIdx.x;
    int p = pred[b * K_ + k];
    __shared__ int sc[K_];
    __shared__ int res[K_];
    sc[k] = p;
    res[k] = k;
    __syncthreads();
    for (int off = 1; off < K_; off <<= 1) {
        int add = (k >= off) ? sc[k - off] : 0;
        __syncthreads();
        sc[k] += add;
        __syncthreads();
    }
    int num = sc[K_ - 1];
    int excl = sc[k] - p;
    if (p == 1) res[excl] = k;
    __syncthreads();
    idxo[b * K_ + k] = (float)((k < num) ? res[k] : k);
    if (k == 0) sum1[b] = (float)num;
}

// ---------------------------------------------------------------------------
// Batched GEMM: Y[b,m,k] = sum_c W[m,c] * X[b,c,k] + bias[m]
// MODE 0: X = concat(X0, X1) along c (CIN=256)
// MODE 1: X = relu(X0 * a[c] + d[c])  (fused BN+relu on load, CIN=128)
// STATS : accumulate per-channel sum / sum^2 of (Y) into sS/sS2 via atomics
// Tiling: BM=128 BN=128 BK=16, 256 threads, 8x8 register tile.
// As row stride = BM+4 = 132 -> every row 16B-aligned for LDS.128.
// ---------------------------------------------------------------------------
template <int CIN, int MODE, int STATS>
__global__ void __launch_bounds__(256)
gemm_kernel(const float* __restrict__ W,
            const float* __restrict__ bias,
            const float* __restrict__ X0,
            const float* __restrict__ X1,
            const float* __restrict__ aa,
            const float* __restrict__ dd,
            float* __restrict__ Y, int M,
            float* __restrict__ sS, float* __restrict__ sS2) {
    const int BM = 128, BN = 128, BK = 16;
    const int AS = BM + 4;            // 132: keeps 16B alignment per row
    __shared__ float As[BK][AS];      // [c][m]
    __shared__ float Bs[BK][BN];      // [c][n]

    int tid = threadIdx.x;
    int b = blockIdx.z;
    int n0 = blockIdx.x * BN;
    int m0 = blockIdx.y * BM;

    float acc[8][8] = {};
    int tm = (tid >> 4) * 8;
    int tn = (tid & 15) * 8;

    // A-load mapping: m = tid>>1 (0..127), c = (tid&1)*8 -> 2 float4 along c
    int am = tid >> 1;
    int ac = (tid & 1) * 8;
    // B-load mapping: c = tid>>4 (0..15), n = (tid&15)*8 -> 2 float4 along n
    int bc = tid >> 4;
    int bn = (tid & 15) * 8;

    for (int c0 = 0; c0 < CIN; c0 += BK) {
        // --- load W tile -> As[c][m] ---
        float4 w0, w1;
        if (m0 + am < M) {
            const float* wp = W + (m0 + am) * CIN + c0 + ac;
            w0 = *reinterpret_cast<const float4*>(wp);
            w1 = *reinterpret_cast<const float4*>(wp + 4);
        } else {
            w0 = make_float4(0.f, 0.f, 0.f, 0.f);
            w1 = w0;
        }
        As[ac + 0][am] = w0.x; As[ac + 1][am] = w0.y;
        As[ac + 2][am] = w0.z; As[ac + 3][am] = w0.w;
        As[ac + 4][am] = w1.x; As[ac + 5][am] = w1.y;
        As[ac + 6][am] = w1.z; As[ac + 7][am] = w1.w;

        // --- load X tile -> Bs[c][n] (coalesced along n) ---
        {
            int cg = c0 + bc;
            float4 v0, v1;
            if (MODE == 0) {
                const float* xp = (cg < C_)
                    ? X0 + b * C_ * K_ + cg * K_ + n0 + bn
                    : X1 + b * C_ * K_ + (cg - C_) * K_ + n0 + bn;
                v0 = *reinterpret_cast<const float4*>(xp);
                v1 = *reinterpret_cast<const float4*>(xp + 4);
            } else {
                const float* xp = X0 + b * C_ * K_ + cg * K_ + n0 + bn;
                v0 = *reinterpret_cast<const float4*>(xp);
                v1 = *reinterpret_cast<const float4*>(xp + 4);
                float av = aa[cg], dv = dd[cg];
                v0.x = fmaxf(fmaf(v0.x, av, dv), 0.f);
                v0.y = fmaxf(fmaf(v0.y, av, dv), 0.f);
                v0.z = fmaxf(fmaf(v0.z, av, dv), 0.f);
                v0.w = fmaxf(fmaf(v0.w, av, dv), 0.f);
                v1.x = fmaxf(fmaf(v1.x, av, dv), 0.f);
                v1.y = fmaxf(fmaf(v1.y, av, dv), 0.f);
                v1.z = fmaxf(fmaf(v1.z, av, dv), 0.f);
                v1.w = fmaxf(fmaf(v1.w, av, dv), 0.f);
            }
            *reinterpret_cast<float4*>(&Bs[bc][bn]) = v0;
            *reinterpret_cast<float4*>(&Bs[bc][bn + 4]) = v1;
        }
        __syncthreads();

#pragma unroll
        for (int kk = 0; kk < BK; kk++) {
            float ra[8], rb[8];
            float4 a0 = *reinterpret_cast<const float4*>(&As[kk][tm]);
            float4 a1 = *reinterpret_cast<const float4*>(&As[kk][tm + 4]);
            float4 b0 = *reinterpret_cast<const float4*>(&Bs[kk][tn]);
            float4 b1 = *reinterpret_cast<const float4*>(&Bs[kk][tn + 4]);
            ra[0] = a0.x; ra[1] = a0.y; ra[2] = a0.z; ra[3] = a0.w;
            ra[4] = a1.x; ra[5] = a1.y; ra[6] = a1.z; ra[7] = a1.w;
            rb[0] = b0.x; rb[1] = b0.y; rb[2] = b0.z; rb[3] = b0.w;
            rb[4] = b1.x; rb[5] = b1.y; rb[6] = b1.z; rb[7] = b1.w;
#pragma unroll
            for (int i = 0; i < 8; i++)
#pragma unroll
                for (int j = 0; j < 8; j++)
                    acc[i][j] = fmaf(ra[i], rb[j], acc[i][j]);
        }
        __syncthreads();
    }

    // --- store (+bias), with fused BN-stat accumulation ---
#pragma unroll
    for (int i = 0; i < 8; i++) {
        int m = m0 + tm + i;
        if (m < M) {
            float bb = __ldg(bias + m);
            float s = 0.f, s2 = 0.f;
            float* yp = Y + b * M * K_ + m * K_ + n0 + tn;
#pragma unroll
            for (int j = 0; j < 8; j++) {
                float v = acc[i][j] + bb;
                yp[j] = v;
                if (STATS) { s += v; s2 = fmaf(v, v, s2); }
            }
            if (STATS) {
                // reduce over the 16 lanes (tid&15) sharing channel m
#pragma unroll
                for (int o = 8; o > 0; o >>= 1) {
                    s  += __shfl_xor_sync(0xffffffffu, s,  o);
                    s2 += __shfl_xor_sync(0xffffffffu, s2, o);
                }
                if ((tid & 15) == 0) {
                    atomicAdd(&sS[m], s);
                    atomicAdd(&sS2[m], s2);
                }
            }
        }
    }
}

// ---------------------------------------------------------------------------
// finalize BN fold: relu_bn(x) = relu(x*a + d)
// ---------------------------------------------------------------------------
__global__ void finalize_kernel(const float* __restrict__ g,
                                const float* __restrict__ be,
                                const float* __restrict__ sS,
                                const float* __restrict__ sS2,
                                float* __restrict__ a, float* __restrict__ d) {
    int c = threadIdx.x;
    if (c < C_) {
        const float invN = 1.0f / (B_ * K_);
        float mean = sS[c] * invN;
        float var = sS2[c] * invN - mean * mean;
        float rstd = rsqrtf(var + 1e-5f);
        float av = rstd * g[c];
        a[c] = av;
        d[c] = be[c] - mean * av;
    }
}

// ---------------------------------------------------------------------------
// Assemble the 183-channel output. SMEM transpose: load g_t coalesced along k,
// write out coalesced along ch. block = (k-chunk of 64, b), 256 threads.
// ---------------------------------------------------------------------------
__global__ void epilogue_kernel(const float* __restrict__ xyz,
                                const float* __restrict__ ms,
                                float* __restrict__ out) {
    __shared__ float s[OUTC * 65];   // [o][k] padded
    __shared__ float sms[54];
    int tid = threadIdx.x;
    int k0 = blockIdx.x * 64;
    int b = blockIdx.y;

    if (tid < 54) sms[tid] = ms[tid];
    const float* tp = g_t + b * OUTC * K_ + k0;
    for (int e = tid; e < OUTC * 64; e += 256) {
        int o = e >> 6, k = e & 63;
        s[o * 65 + k] = tp[o * K_ + k];
    }
    __syncthreads();

    float* op = out + (b * K_ + k0) * OCH;
    for (int e = tid; e < 64 * OCH; e += 256) {
        int k = e / OCH;
        int ch = e - k * OCH;
        int o;
        float scale = 1.f, add = 0.f;
        if (ch < 27) {               // center(+xyz), hs, hrn
            o = ch;
            if (ch < 3) add = xyz[(b * K_ + k0 + k) * 3 + ch];
        } else if (ch < 39) {        // hr = hrn * pi/12
            o = ch - 12;
            scale = 0.26179938779914943f;
        } else if (ch < 111) {       // ss, srn
            o = ch - 12;
        } else if (ch < 165) {       // sr = srn * mean_size
            o = ch - 66;
            scale = sms[ch - 111];
        } else {                     // sem
            o = ch - 66;
        }
        op[e] = s[o * 65 + k] * scale + add;
    }
}

// ---------------------------------------------------------------------------
extern "C" void kernel_launch(void* const* d_in, const int* in_sizes, int n_in,
                              void* d_out, int out_size) {
    (void)in_sizes; (void)n_in; (void)out_size;
    const float* xyz      = (const float*)d_in[0];
    const float* features = (const float*)d_in[1];
    const float* rn       = (const float*)d_in[2];
    const float* gt       = (const float*)d_in[3];
    const int*   pred     = (const int*)d_in[4];   // int32
    const float* W1 = (const float*)d_in[5];
    const float* b1 = (const float*)d_in[6];
    const float* g1 = (const float*)d_in[7];
    const float* be1 = (const float*)d_in[8];
    const float* W2 = (const float*)d_in[9];
    const float* b2 = (const float*)d_in[10];
    const float* g2 = (const float*)d_in[11];
    const float* be2 = (const float*)d_in[12];
    const float* W3 = (const float*)d_in[13];
    const float* b3 = (const float*)d_in[14];
    const float* ms = (const float*)d_in[15];
    float* out = (float*)d_out;

    const int OFF_IDX = B_ * K_ * OCH;           // 11993088
    const int OFF_SUM = OFF_IDX + B_ * K_;       // 12058624
    const int OFF_LBL = OFF_SUM + B_;            // 12058880

    float *p_net1, *p_net2, *p_t, *p_s, *p_s2, *p_a, *p_d;
    cudaGetSymbolAddress((void**)&p_net1, g_net1);
    cudaGetSymbolAddress((void**)&p_net2, g_net2);
    cudaGetSymbolAddress((void**)&p_t,    g_t);
    cudaGetSymbolAddress((void**)&p_s,    g_s);
    cudaGetSymbolAddress((void**)&p_s2,   g_s2);
    cudaGetSymbolAddress((void**)&p_a,    g_a);
    cudaGetSymbolAddress((void**)&p_d,    g_d);

    zero_kernel<<<1, 128>>>();
    label_kernel<<<B_, K_>>>(xyz, gt, out + OFF_LBL);
    index_kernel<<<B_, K_>>>(pred, out + OFF_IDX, out + OFF_SUM);

    dim3 gg(K_ / 128, 1, B_);  // (n-tiles, m-tiles, batch)
    gemm_kernel<256, 0, 1><<<gg, 256>>>(W1, b1, features, rn, nullptr, nullptr,
                                        p_net1, C_, p_s, p_s2);
    finalize_kernel<<<1, 128>>>(g1, be1, p_s, p_s2, p_a, p_d);
    gemm_kernel<128, 1, 1><<<gg, 256>>>(W2, b2, p_net1, nullptr, p_a, p_d,
                                        p_net2, C_, p_s + C_, p_s2 + C_);
    finalize_kernel<<<1, 128>>>(g2, be2, p_s + C_, p_s2 + C_, p_a + C_, p_d + C_);
    gemm_kernel<128, 1, 0><<<gg, 256>>>(W3, b3, p_net2, nullptr, p_a + C_, p_d + C_,
                                        p_t, OUTC, nullptr, nullptr);

    epilogue_kernel<<<dim3(K_ / 64, B_), 256>>>(xyz, ms, out);
}